// round 8
// baseline (speedup 1.0000x reference)
#include <cuda_runtime.h>
#include <cuda_fp16.h>
#include <cstdint>

// Problem constants
#define BATCH   32
#define NPATCH  576
#define MTOT    (BATCH * NPATCH)   // 18432
#define KDIM    768                // 3*16*16
#define EMBED   768

// ---------------------------------------------------------------------------
// Scratch (device globals: allocation-free rule). Single fp16 A and B.
// ---------------------------------------------------------------------------
__device__ __align__(16) __half g_A[(size_t)MTOT * KDIM];
__device__ __align__(16) __half g_B[(size_t)EMBED * KDIM];

// ---------------------------------------------------------------------------
// Helpers (base sm_103-target-legal only)
// ---------------------------------------------------------------------------
__device__ __forceinline__ uint32_t smem_u32(const void* p) {
    uint32_t a;
    asm("{ .reg .u64 t; cvta.to.shared.u64 t, %1; cvt.u32.u64 %0, t; }" : "=r"(a) : "l"(p));
    return a;
}

__device__ __forceinline__ void cp16(uint32_t dst, const void* src) {
    asm volatile("cp.async.cg.shared.global [%0], [%1], 16;\n" :: "r"(dst), "l"(src));
}
#define CP_COMMIT() asm volatile("cp.async.commit_group;\n" ::: "memory")
#define CP_WAIT(n)  asm volatile("cp.async.wait_group %0;\n" :: "n"(n) : "memory")

#define LDSM_X4(r, addr)                                                        \
    asm volatile("ldmatrix.sync.aligned.m8n8.x4.shared.b16 {%0,%1,%2,%3}, [%4];" \
        : "=r"((r)[0]), "=r"((r)[1]), "=r"((r)[2]), "=r"((r)[3]) : "r"(addr))

// fp16-accumulate MMA: D(f16x2 pair) = A*B + D. Runs at 2x the f32-acc rate.
#define MMA_F16ACC(d, a, b0, b1)                                                \
    asm volatile("mma.sync.aligned.m16n8k16.row.col.f16.f16.f16.f16 "           \
        "{%0,%1}, {%2,%3,%4,%5}, {%6,%7}, {%0,%1};"                             \
        : "+r"((d)[0]), "+r"((d)[1])                                            \
        : "r"((a)[0]), "r"((a)[1]), "r"((a)[2]), "r"((a)[3]), "r"(b0), "r"(b1))

// ---------------------------------------------------------------------------
// Kernel 1 (fused): blocks [0,2304): gather patches -> fp16 A [18432, 768]
//                   blocks [2304,3456): proj_w -> fp16 B [768, 768]
// ---------------------------------------------------------------------------
template <int S>
__device__ __forceinline__ void convert_pairs(const float (&e)[20], unsigned (&uh)[8]) {
#pragma unroll
    for (int k = 0; k < 8; k++) {
        __half2 hp = __halves2half2(__float2half_rn(e[S + 2 * k]),
                                    __float2half_rn(e[S + 2 * k + 1]));
        uh[k] = *reinterpret_cast<unsigned*>(&hp);
    }
}

__global__ __launch_bounds__(256) void prep_kernel(const float* __restrict__ x,
                                                   const int* __restrict__ h_idx,
                                                   const int* __restrict__ w_idx,
                                                   const float* __restrict__ pw) {
    if (blockIdx.x >= 2304) {
        int i = (blockIdx.x - 2304) * 256 + threadIdx.x;
        float2 v = reinterpret_cast<const float2*>(pw)[i];
        __half2 hp = __halves2half2(__float2half_rn(v.x), __float2half_rn(v.y));
        reinterpret_cast<unsigned*>(g_B)[i] = *reinterpret_cast<unsigned*>(&hp);
        return;
    }
    int warp = (blockIdx.x << 3) + (threadIdx.x >> 5);   // 0..18431
    int lane = threadIdx.x & 31;
    int b = warp / NPATCH;
    int h = h_idx[warp];
    int w = w_idx[warp];
    int s  = w & 3;
    int a0 = w & ~3;
    const float* xb = x + (size_t)b * (3 * 384 * 384);
    __half* oh = g_A + (size_t)warp * KDIM;

#pragma unroll
    for (int pass = 0; pass < 2; ++pass) {
        int rr = (pass << 5) + lane;          // row task 0..47  (c*16 + ph)
        if (rr < 48) {
            int c = rr >> 4, ph = rr & 15;
            const float4* src = reinterpret_cast<const float4*>(
                xb + (size_t)(c * 384 + h + ph) * 384 + a0);
            float4 f0 = src[0], f1 = src[1], f2 = src[2], f3 = src[3];
            float4 f4 = make_float4(0.f, 0.f, 0.f, 0.f);
            if (s != 0) f4 = src[4];
            float e[20] = {f0.x, f0.y, f0.z, f0.w, f1.x, f1.y, f1.z, f1.w,
                           f2.x, f2.y, f2.z, f2.w, f3.x, f3.y, f3.z, f3.w,
                           f4.x, f4.y, f4.z, f4.w};
            unsigned uh[8];
            switch (s) {
                case 0:  convert_pairs<0>(e, uh); break;
                case 1:  convert_pairs<1>(e, uh); break;
                case 2:  convert_pairs<2>(e, uh); break;
                default: convert_pairs<3>(e, uh); break;
            }
            uint4* dh = reinterpret_cast<uint4*>(oh + rr * 16);
            dh[0] = make_uint4(uh[0], uh[1], uh[2], uh[3]);
            dh[1] = make_uint4(uh[4], uh[5], uh[6], uh[7]);
        }
    }
}

// ---------------------------------------------------------------------------
// Kernel 2: GEMM. BM=128, BN=128, BK=32, 8 warps (4m x 2n, 32x64 warp tiles),
// 2 CTAs/SM, 5-stage cp.async ring. fp16-accumulate MMAs (2x rate vs f32-acc),
// chained 4 deep (64 k-elems), promoted into f32 accumulators every 2 ktiles.
// ---------------------------------------------------------------------------
static constexpr int ROW_B     = 80;
static constexpr int MAT_BYTES = 128 * ROW_B;       // 10240
static constexpr int OFF_A = 0;
static constexpr int OFF_B = MAT_BYTES;
static constexpr int STAGE_BYTES = 2 * MAT_BYTES;   // 20480
static constexpr int N_STAGE = 5;
static constexpr int GEMM_SMEM = N_STAGE * STAGE_BYTES;  // 102400 (x2 CTAs = 200KB/SM)
static constexpr int KTILES = 24;

__device__ __forceinline__ void stage(uint32_t sbuf, int kt, int mbase, int nbase, int tid) {
    const __half* ga = g_A + (size_t)mbase * KDIM + kt * 32;
    const __half* gb = g_B + (size_t)nbase * KDIM + kt * 32;
#pragma unroll
    for (int i = 0; i < 2; i++) {
        int idx = tid + i * 256;              // 0..511 = 128 rows x 4 segs
        int row = idx >> 2, seg = idx & 3;
        uint32_t off = (uint32_t)(row * ROW_B + seg * 16);
        size_t g = (size_t)row * KDIM + seg * 8;
        cp16(sbuf + OFF_A + off, ga + g);
        cp16(sbuf + OFF_B + off, gb + g);
    }
}

__device__ __forceinline__ void load_frags(uint32_t (&fa)[2][4], uint32_t (&fb)[4][4],
                                           uint32_t a_base, uint32_t b_base) {
    LDSM_X4(fa[0], a_base);
    LDSM_X4(fa[1], a_base + 16 * ROW_B);
#pragma unroll
    for (int nb = 0; nb < 4; nb++) LDSM_X4(fb[nb], b_base + nb * 16 * ROW_B);
}

// 16 independent fp16-acc chains (one per (mf,nf) fragment)
__device__ __forceinline__ void mma_all_h(uint32_t (&hacc)[2][8][2],
                                          uint32_t (&fa)[2][4], uint32_t (&fb)[4][4]) {
#pragma unroll
    for (int mf = 0; mf < 2; mf++)
#pragma unroll
        for (int nf = 0; nf < 8; nf++) {
            int nb = nf >> 1, sel = nf & 1;
            MMA_F16ACC(hacc[mf][nf], fa[mf], fb[nb][sel], fb[nb][2 + sel]);
        }
}

__device__ __forceinline__ void promote(float (&acc)[2][8][4], uint32_t (&hacc)[2][8][2]) {
#pragma unroll
    for (int mf = 0; mf < 2; mf++)
#pragma unroll
        for (int nf = 0; nf < 8; nf++) {
            float2 p0 = __half22float2(*reinterpret_cast<__half2*>(&hacc[mf][nf][0]));
            float2 p1 = __half22float2(*reinterpret_cast<__half2*>(&hacc[mf][nf][1]));
            acc[mf][nf][0] += p0.x;
            acc[mf][nf][1] += p0.y;
            acc[mf][nf][2] += p1.x;
            acc[mf][nf][3] += p1.y;
            hacc[mf][nf][0] = 0u;
            hacc[mf][nf][1] = 0u;
        }
}

__global__ __launch_bounds__(256, 2) void gemm_kernel(const float* __restrict__ proj_b,
                                                      float* __restrict__ out) {
    extern __shared__ char smem[];
    uint32_t sb = smem_u32(smem);
    int tid = threadIdx.x;
    int lane = tid & 31, wid = tid >> 5;
    int wm = wid & 3, wn = wid >> 2;
    int nbase = blockIdx.x * 128;      // x fastest: 6 CTAs share one A tile in L2
    int mbase = blockIdx.y * 128;

    float acc[2][8][4];
    uint32_t hacc[2][8][2];
#pragma unroll
    for (int a = 0; a < 2; a++)
#pragma unroll
        for (int b = 0; b < 8; b++) {
#pragma unroll
            for (int c = 0; c < 4; c++) acc[a][b][c] = 0.f;
            hacc[a][b][0] = 0u;
            hacc[a][b][1] = 0u;
        }

    int r15 = lane & 15;
    uint32_t khalf = (uint32_t)((lane >> 4) * 16);
    uint32_t a0 = sb + OFF_A + (uint32_t)((wm * 32 + r15) * ROW_B) + khalf;
    uint32_t b0 = sb + OFF_B + (uint32_t)((wn * 64 + r15) * ROW_B) + khalf;

    uint32_t fa[2][4], fb[4][4];   // single fragment set (16 indep chains hide LDSM)

    // Prologue: fill 4 of 5 ring slots, ensure tile 0 complete.
    stage(sb, 0, mbase, nbase, tid);                   CP_COMMIT();
    stage(sb + STAGE_BYTES, 1, mbase, nbase, tid);     CP_COMMIT();
    stage(sb + 2 * STAGE_BYTES, 2, mbase, nbase, tid); CP_COMMIT();
    stage(sb + 3 * STAGE_BYTES, 3, mbase, nbase, tid); CP_COMMIT();
    CP_WAIT(3);
    __syncthreads();

#pragma unroll
    for (int kt = 0; kt < KTILES; kt++) {
        const uint32_t slot = sb + (uint32_t)((kt % N_STAGE) * STAGE_BYTES);
        // ks0: load frags, 16 fp16-acc MMAs
        load_frags(fa, fb, a0 + (slot - sb), b0 + (slot - sb));
        mma_all_h(hacc, fa, fb);
        // ks1: reuse frag regs, 16 more (chain depth 2 per ktile)
        load_frags(fa, fb, a0 + (slot - sb) + 32, b0 + (slot - sb) + 32);
        mma_all_h(hacc, fa, fb);
        // promote fp16 chains into f32 every 2 ktiles (chain depth 4)
        if (kt & 1) promote(acc, hacc);
        // refill ring slot (kt+4)%5 (last read at iter kt-1, fenced by its barrier)
        if (kt + 4 < KTILES) {
            stage(sb + (uint32_t)(((kt + 4) % N_STAGE) * STAGE_BYTES), kt + 4, mbase, nbase, tid);
            CP_COMMIT();
        }
        if (kt < KTILES - 1) {
            // need tile kt+1 complete before next iteration's LDSM
            if (kt + 4 < KTILES)           { CP_WAIT(3); }
            else if (kt + 4 == KTILES)     { CP_WAIT(2); }
            else if (kt + 4 == KTILES + 1) { CP_WAIT(1); }
            else                           { CP_WAIT(0); }
            __syncthreads();
        }
    }

    // Epilogue: acc + bias -> out
#pragma unroll
    for (int mf = 0; mf < 2; mf++) {
#pragma unroll
        for (int nf = 0; nf < 8; nf++) {
            int row = mbase + wm * 32 + mf * 16 + (lane >> 2);
            int col = nbase + wn * 64 + nf * 8 + (lane & 3) * 2;
            float2 bv = *reinterpret_cast<const float2*>(proj_b + col);
            float2 o0 = make_float2(acc[mf][nf][0] + bv.x, acc[mf][nf][1] + bv.y);
            float2 o1 = make_float2(acc[mf][nf][2] + bv.x, acc[mf][nf][3] + bv.y);
            *reinterpret_cast<float2*>(out + (size_t)row * EMBED + col) = o0;
            *reinterpret_cast<float2*>(out + (size_t)(row + 8) * EMBED + col) = o1;
        }
    }
}

// ---------------------------------------------------------------------------
// kernel_launch
// ---------------------------------------------------------------------------
extern "C" void kernel_launch(void* const* d_in, const int* in_sizes, int n_in,
                              void* d_out, int out_size) {
    const float* x      = (const float*)d_in[0];
    const int*   h_idx  = (const int*)d_in[1];
    const int*   w_idx  = (const int*)d_in[2];
    const float* proj_w = (const float*)d_in[3];
    const float* proj_b = (const float*)d_in[4];
    float* out = (float*)d_out;

    prep_kernel<<<3456, 256>>>(x, h_idx, w_idx, proj_w);  // gather + B prep fused

    cudaFuncSetAttribute(gemm_kernel, cudaFuncAttributeMaxDynamicSharedMemorySize, GEMM_SMEM);
    gemm_kernel<<<dim3(6, 144), 256, GEMM_SMEM>>>(proj_b, out);
}

// round 9
// speedup vs baseline: 1.1957x; 1.1957x over previous
#include <cuda_runtime.h>
#include <cuda_fp16.h>
#include <cstdint>

// Problem constants
#define BATCH   32
#define NPATCH  576
#define MTOT    (BATCH * NPATCH)   // 18432
#define KDIM    768                // 3*16*16
#define EMBED   768
#define NKT2    12                 // super-k-tiles of 64

// ---------------------------------------------------------------------------
// Scratch, k-major + XOR-swizzled so GEMM tiles are CONTIGUOUS 16KB blocks:
//   g_A2[kt2][patch][64]  (128B per row, quad q stored at q ^ (row&7))
//   g_B2[kt2][e][64]
// ---------------------------------------------------------------------------
__device__ __align__(256) __half g_A2[(size_t)NKT2 * MTOT * 64];
__device__ __align__(256) __half g_B2[(size_t)NKT2 * EMBED * 64];

// ---------------------------------------------------------------------------
// Helpers (base sm_103-target-legal: mbarrier + cp.async.bulk are sm_90 base)
// ---------------------------------------------------------------------------
__device__ __forceinline__ uint32_t smem_u32(const void* p) {
    uint32_t a;
    asm("{ .reg .u64 t; cvta.to.shared.u64 t, %1; cvt.u32.u64 %0, t; }" : "=r"(a) : "l"(p));
    return a;
}

#define MBAR_INIT(addr, cnt) \
    asm volatile("mbarrier.init.shared.b64 [%0], %1;" :: "r"(addr), "r"(cnt) : "memory")

#define MBAR_EXPECT_TX(addr, bytes) \
    asm volatile("mbarrier.arrive.expect_tx.shared.b64 _, [%0], %1;" \
                 :: "r"(addr), "r"(bytes) : "memory")

#define MBAR_WAIT_PARITY(mbar_addr, parity) do {                                        \
    uint32_t _mbar = (uint32_t)(mbar_addr);                                             \
    uint32_t _par  = (uint32_t)(parity);                                                \
    uint32_t _done;                                                                     \
    asm volatile("{\n\t.reg .pred p;\n\t"                                               \
        "mbarrier.try_wait.parity.acquire.cta.shared::cta.b64 p, [%1], %2;\n\t"         \
        "selp.b32 %0, 1, 0, p;\n\t}"                                                    \
        : "=r"(_done) : "r"(_mbar), "r"(_par) : "memory");                              \
    if (!_done) {                                                                       \
        asm volatile("{\n\t.reg .pred P1;\n\t"                                          \
            "WL_%=:\n\t"                                                                \
            "mbarrier.try_wait.parity.acquire.cta.shared::cta.b64 P1, [%0], %1, 0x989680;\n\t" \
            "@P1 bra.uni WD_%=;\n\t"                                                    \
            "bra.uni WL_%=;\n\t"                                                        \
            "WD_%=:\n\t}"                                                               \
            :: "r"(_mbar), "r"(_par) : "memory");                                       \
    }                                                                                   \
} while (0)

#define BULK_G2S(dst, src, bytes, mbar)                                                 \
    asm volatile("cp.async.bulk.shared::cluster.global.mbarrier::complete_tx::bytes "   \
        "[%0], [%1], %2, [%3];"                                                         \
        :: "r"(dst), "l"(src), "r"(bytes), "r"(mbar) : "memory")

#define FENCE_ASYNC() asm volatile("fence.proxy.async.shared::cta;" ::: "memory")

#define LDSM_X4(r, addr)                                                        \
    asm volatile("ldmatrix.sync.aligned.m8n8.x4.shared.b16 {%0,%1,%2,%3}, [%4];" \
        : "=r"((r)[0]), "=r"((r)[1]), "=r"((r)[2]), "=r"((r)[3]) : "r"(addr))

#define MMA_F16(d, a, b0, b1)                                                   \
    asm volatile("mma.sync.aligned.m16n8k16.row.col.f32.f16.f16.f32 "           \
        "{%0,%1,%2,%3}, {%4,%5,%6,%7}, {%8,%9}, {%0,%1,%2,%3};"                 \
        : "+f"((d)[0]), "+f"((d)[1]), "+f"((d)[2]), "+f"((d)[3])                \
        : "r"((a)[0]), "r"((a)[1]), "r"((a)[2]), "r"((a)[3]), "r"(b0), "r"(b1))

// ---------------------------------------------------------------------------
// Kernel 1 (fused): blocks [0,2304): gather -> g_A2 (k-major swizzled)
//                   blocks [2304,2592): proj_w -> g_B2 (k-major swizzled)
// ---------------------------------------------------------------------------
template <int S>
__device__ __forceinline__ void convert_pairs(const float (&e)[20], unsigned (&uh)[8]) {
#pragma unroll
    for (int k = 0; k < 8; k++) {
        __half2 hp = __halves2half2(__float2half_rn(e[S + 2 * k]),
                                    __float2half_rn(e[S + 2 * k + 1]));
        uh[k] = *reinterpret_cast<unsigned*>(&hp);
    }
}

__global__ __launch_bounds__(256) void prep_kernel(const float* __restrict__ x,
                                                   const int* __restrict__ h_idx,
                                                   const int* __restrict__ w_idx,
                                                   const float* __restrict__ pw) {
    if (blockIdx.x >= 2304) {
        // ---- B prep: one thread per 16B quad (8 floats -> 8 fp16) ----
        int i = (blockIdx.x - 2304) * 256 + threadIdx.x;   // [0, 73728)
        int e  = i / 96;            // output row 0..767
        int g  = i - e * 96;        // quad-in-row 0..95
        int kt2 = g >> 3, q = g & 7;
        const float4* s = reinterpret_cast<const float4*>(pw + (size_t)e * KDIM + kt2 * 64 + q * 8);
        float4 v0 = s[0], v1 = s[1];
        __half2 h0 = __halves2half2(__float2half_rn(v0.x), __float2half_rn(v0.y));
        __half2 h1 = __halves2half2(__float2half_rn(v0.z), __float2half_rn(v0.w));
        __half2 h2 = __halves2half2(__float2half_rn(v1.x), __float2half_rn(v1.y));
        __half2 h3 = __halves2half2(__float2half_rn(v1.z), __float2half_rn(v1.w));
        __half* dst = g_B2 + ((size_t)kt2 * EMBED + e) * 64 + ((q ^ (e & 7)) << 3);
        *reinterpret_cast<uint4*>(dst) = make_uint4(
            *reinterpret_cast<unsigned*>(&h0), *reinterpret_cast<unsigned*>(&h1),
            *reinterpret_cast<unsigned*>(&h2), *reinterpret_cast<unsigned*>(&h3));
        return;
    }
    // ---- gather: one warp per patch ----
    int warp = (blockIdx.x << 3) + (threadIdx.x >> 5);   // 0..18431
    int lane = threadIdx.x & 31;
    int b = warp / NPATCH;
    int h = h_idx[warp];
    int w = w_idx[warp];
    int s  = w & 3;
    int a0 = w & ~3;
    int p7 = warp & 7;
    const float* xb = x + (size_t)b * (3 * 384 * 384);

#pragma unroll
    for (int pass = 0; pass < 2; ++pass) {
        int rr = (pass << 5) + lane;          // row task 0..47  (c*16 + ph)
        if (rr < 48) {
            int c = rr >> 4, ph = rr & 15;
            const float4* src = reinterpret_cast<const float4*>(
                xb + (size_t)(c * 384 + h + ph) * 384 + a0);
            float4 f0 = src[0], f1 = src[1], f2 = src[2], f3 = src[3];
            float4 f4 = make_float4(0.f, 0.f, 0.f, 0.f);
            if (s != 0) f4 = src[4];
            float e[20] = {f0.x, f0.y, f0.z, f0.w, f1.x, f1.y, f1.z, f1.w,
                           f2.x, f2.y, f2.z, f2.w, f3.x, f3.y, f3.z, f3.w,
                           f4.x, f4.y, f4.z, f4.w};
            unsigned uh[8];
            switch (s) {
                case 0:  convert_pairs<0>(e, uh); break;
                case 1:  convert_pairs<1>(e, uh); break;
                case 2:  convert_pairs<2>(e, uh); break;
                default: convert_pairs<3>(e, uh); break;
            }
            // f base = rr*16: super-tile kt2 = rr>>2, first quad q0 = (rr&3)*2
            int kt2 = rr >> 2, q0 = (rr & 3) * 2;
            __half* dst = g_A2 + ((size_t)kt2 * MTOT + warp) * 64;
            *reinterpret_cast<uint4*>(dst + ((q0 ^ p7) << 3)) =
                make_uint4(uh[0], uh[1], uh[2], uh[3]);
            *reinterpret_cast<uint4*>(dst + (((q0 + 1) ^ p7) << 3)) =
                make_uint4(uh[4], uh[5], uh[6], uh[7]);
        }
    }
}

// ---------------------------------------------------------------------------
// Kernel 2: GEMM. BM=128, BN=128, BK=64 super-tiles, 8 warps (4m x 2n),
// 2 CTAs/SM. Staging: cp.async.bulk (2 x 16KB per super-ktile) + mbarrier —
// removes the 21M-LDGSTS LSU-issue bottleneck that pinned R5/R7 at 72us.
// ---------------------------------------------------------------------------
static constexpr int SLOT_BYTES = 32768;     // A 16KB + B 16KB
static constexpr int N_SLOT = 3;
static constexpr int GEMM_SMEM = 128 + N_SLOT * SLOT_BYTES;  // 98432 (2 CTAs/SM)

__device__ __forceinline__ void load_frags(uint32_t (&fa)[2][4], uint32_t (&fb)[4][4],
                                           uint32_t a_base, uint32_t b_base, uint32_t xq) {
    LDSM_X4(fa[0], a_base + xq);
    LDSM_X4(fa[1], a_base + 2048 + xq);
#pragma unroll
    for (int nb = 0; nb < 4; nb++) LDSM_X4(fb[nb], b_base + nb * 2048 + xq);
}

__device__ __forceinline__ void mma_all(float (&acc)[2][8][4],
                                        uint32_t (&fa)[2][4], uint32_t (&fb)[4][4]) {
#pragma unroll
    for (int mf = 0; mf < 2; mf++)
#pragma unroll
        for (int nf = 0; nf < 8; nf++) {
            int nb = nf >> 1, sel = nf & 1;
            MMA_F16(acc[mf][nf], fa[mf], fb[nb][sel], fb[nb][2 + sel]);
        }
}

__global__ __launch_bounds__(256, 2) void gemm_kernel(const float* __restrict__ proj_b,
                                                      float* __restrict__ out) {
    extern __shared__ char smem[];
    uint32_t sb = smem_u32(smem);
    int tid = threadIdx.x;
    int lane = tid & 31, wid = tid >> 5;
    int wm = wid & 3, wn = wid >> 2;
    int nbase = blockIdx.x * 128;      // x fastest: 6 CTAs share one A tile in L2
    int mbase = blockIdx.y * 128;

    float acc[2][8][4];
#pragma unroll
    for (int a = 0; a < 2; a++)
#pragma unroll
        for (int b = 0; b < 8; b++)
#pragma unroll
            for (int c = 0; c < 4; c++) acc[a][b][c] = 0.f;

    int l15 = lane & 15, kh = lane >> 4, l7 = lane & 7;
    uint32_t base = sb + 128;
    uint32_t a_off = base + (uint32_t)((wm * 32 + l15) * 128);          // A at slot+0
    uint32_t b_off = base + 16384 + (uint32_t)((wn * 64 + l15) * 128);  // B at slot+16KB
    // per-k16-step swizzled quad byte offset
    uint32_t xq[4];
#pragma unroll
    for (int ks = 0; ks < 4; ks++) xq[ks] = (uint32_t)(((ks * 2 + kh) ^ l7) << 4);

    const char* srcA = reinterpret_cast<const char*>(g_A2) + (size_t)mbase * 128;
    const char* srcB = reinterpret_cast<const char*>(g_B2) + (size_t)nbase * 128;
    const size_t strideA = (size_t)MTOT * 128;   // bytes per super-ktile of A
    const size_t strideB = (size_t)EMBED * 128;

    if (tid == 0) {
#pragma unroll
        for (int s = 0; s < N_SLOT; s++) MBAR_INIT(sb + s * 8, 1u);
    }
    __syncthreads();
    if (tid == 0) {
#pragma unroll
        for (int s = 0; s < 2; s++) {
            MBAR_EXPECT_TX(sb + s * 8, (uint32_t)SLOT_BYTES);
            BULK_G2S(base + s * SLOT_BYTES,         srcA + s * strideA, 16384u, sb + s * 8);
            BULK_G2S(base + s * SLOT_BYTES + 16384, srcB + s * strideB, 16384u, sb + s * 8);
        }
    }

    uint32_t xa[2][4], xb[4][4];   // fragment buffer X
    uint32_t ya[2][4], yb[4][4];   // fragment buffer Y

    MBAR_WAIT_PARITY(sb + 0, 0);
    __syncthreads();
    load_frags(xa, xb, a_off, b_off, xq[0]);

#pragma unroll
    for (int kt = 0; kt < NKT2; kt++) {
        const uint32_t slot = (uint32_t)((kt % N_SLOT) * SLOT_BYTES);
        // 4 k16-steps, X/Y alternating; LDSM hidden under 16-MMA bursts
        load_frags(ya, yb, a_off + slot, b_off + slot, xq[1]);
        mma_all(acc, xa, xb);
        load_frags(xa, xb, a_off + slot, b_off + slot, xq[2]);
        mma_all(acc, ya, yb);
        load_frags(ya, yb, a_off + slot, b_off + slot, xq[3]);
        mma_all(acc, xa, xb);
        if (kt + 2 < NKT2) {
            // refill slot (kt+2)%3: its readers (tile kt-1) all finished before
            // iter kt-1's __syncthreads -> WAR safe.
            if (tid == 0) {
                FENCE_ASYNC();
                uint32_t m = sb + ((kt + 2) % N_SLOT) * 8;
                MBAR_EXPECT_TX(m, (uint32_t)SLOT_BYTES);
                BULK_G2S(base + ((kt + 2) % N_SLOT) * SLOT_BYTES,
                         srcA + (size_t)(kt + 2) * strideA, 16384u, m);
                BULK_G2S(base + ((kt + 2) % N_SLOT) * SLOT_BYTES + 16384,
                         srcB + (size_t)(kt + 2) * strideB, 16384u, m);
            }
        }
        if (kt < NKT2 - 1) {
            MBAR_WAIT_PARITY(sb + ((kt + 1) % N_SLOT) * 8, ((kt + 1) / N_SLOT) & 1);
            __syncthreads();
            const uint32_t nslot = (uint32_t)(((kt + 1) % N_SLOT) * SLOT_BYTES);
            load_frags(xa, xb, a_off + nslot, b_off + nslot, xq[0]);
        }
        mma_all(acc, ya, yb);
    }

    // Epilogue: acc + bias -> out
#pragma unroll
    for (int mf = 0; mf < 2; mf++) {
#pragma unroll
        for (int nf = 0; nf < 8; nf++) {
            int row = mbase + wm * 32 + mf * 16 + (lane >> 2);
            int col = nbase + wn * 64 + nf * 8 + (lane & 3) * 2;
            float2 bv = *reinterpret_cast<const float2*>(proj_b + col);
            float2 o0 = make_float2(acc[mf][nf][0] + bv.x, acc[mf][nf][1] + bv.y);
            float2 o1 = make_float2(acc[mf][nf][2] + bv.x, acc[mf][nf][3] + bv.y);
            *reinterpret_cast<float2*>(out + (size_t)row * EMBED + col) = o0;
            *reinterpret_cast<float2*>(out + (size_t)(row + 8) * EMBED + col) = o1;
        }
    }
}

// ---------------------------------------------------------------------------
// kernel_launch
// ---------------------------------------------------------------------------
extern "C" void kernel_launch(void* const* d_in, const int* in_sizes, int n_in,
                              void* d_out, int out_size) {
    const float* x      = (const float*)d_in[0];
    const int*   h_idx  = (const int*)d_in[1];
    const int*   w_idx  = (const int*)d_in[2];
    const float* proj_w = (const float*)d_in[3];
    const float* proj_b = (const float*)d_in[4];
    float* out = (float*)d_out;

    prep_kernel<<<2592, 256>>>(x, h_idx, w_idx, proj_w);  // gather + B prep fused

    cudaFuncSetAttribute(gemm_kernel, cudaFuncAttributeMaxDynamicSharedMemorySize, GEMM_SMEM);
    gemm_kernel<<<dim3(6, 144), 256, GEMM_SMEM>>>(proj_b, out);
}

// round 10
// speedup vs baseline: 1.2690x; 1.0613x over previous
#include <cuda_runtime.h>
#include <cuda_fp16.h>
#include <cstdint>

// Problem constants
#define BATCH   32
#define NPATCH  576
#define MTOT    (BATCH * NPATCH)   // 18432
#define KDIM    768                // 3*16*16
#define EMBED   768
#define NKT2    12                 // super-k-tiles of 64

// ---------------------------------------------------------------------------
// Scratch, k-major + XOR-swizzled so GEMM tiles are CONTIGUOUS 16KB blocks:
//   g_A2[kt2][patch][64]  (128B per row, quad q stored at q ^ (row&7))
//   g_B2[kt2][e][64]
// ---------------------------------------------------------------------------
__device__ __align__(256) __half g_A2[(size_t)NKT2 * MTOT * 64];
__device__ __align__(256) __half g_B2[(size_t)NKT2 * EMBED * 64];

// ---------------------------------------------------------------------------
// Helpers (base sm_103-target-legal: mbarrier + cp.async.bulk are sm_90 base)
// ---------------------------------------------------------------------------
__device__ __forceinline__ uint32_t smem_u32(const void* p) {
    uint32_t a;
    asm("{ .reg .u64 t; cvta.to.shared.u64 t, %1; cvt.u32.u64 %0, t; }" : "=r"(a) : "l"(p));
    return a;
}

#define MBAR_INIT(addr, cnt) \
    asm volatile("mbarrier.init.shared.b64 [%0], %1;" :: "r"(addr), "r"(cnt) : "memory")

#define MBAR_ARRIVE(addr) \
    asm volatile("mbarrier.arrive.shared.b64 _, [%0];" :: "r"(addr) : "memory")

#define MBAR_EXPECT_TX(addr, bytes) \
    asm volatile("mbarrier.arrive.expect_tx.shared.b64 _, [%0], %1;" \
                 :: "r"(addr), "r"(bytes) : "memory")

#define MBAR_WAIT_PARITY(mbar_addr, parity) do {                                        \
    uint32_t _mbar = (uint32_t)(mbar_addr);                                             \
    uint32_t _par  = (uint32_t)(parity);                                                \
    uint32_t _done;                                                                     \
    asm volatile("{\n\t.reg .pred p;\n\t"                                               \
        "mbarrier.try_wait.parity.acquire.cta.shared::cta.b64 p, [%1], %2;\n\t"         \
        "selp.b32 %0, 1, 0, p;\n\t}"                                                    \
        : "=r"(_done) : "r"(_mbar), "r"(_par) : "memory");                              \
    if (!_done) {                                                                       \
        asm volatile("{\n\t.reg .pred P1;\n\t"                                          \
            "WL_%=:\n\t"                                                                \
            "mbarrier.try_wait.parity.acquire.cta.shared::cta.b64 P1, [%0], %1, 0x989680;\n\t" \
            "@P1 bra.uni WD_%=;\n\t"                                                    \
            "bra.uni WL_%=;\n\t"                                                        \
            "WD_%=:\n\t}"                                                               \
            :: "r"(_mbar), "r"(_par) : "memory");                                       \
    }                                                                                   \
} while (0)

#define BULK_G2S(dst, src, bytes, mbar)                                                 \
    asm volatile("cp.async.bulk.shared::cluster.global.mbarrier::complete_tx::bytes "   \
        "[%0], [%1], %2, [%3];"                                                         \
        :: "r"(dst), "l"(src), "r"(bytes), "r"(mbar) : "memory")

#define FENCE_ASYNC() asm volatile("fence.proxy.async.shared::cta;" ::: "memory")

#define LDSM_X4(r, addr)                                                        \
    asm volatile("ldmatrix.sync.aligned.m8n8.x4.shared.b16 {%0,%1,%2,%3}, [%4];" \
        : "=r"((r)[0]), "=r"((r)[1]), "=r"((r)[2]), "=r"((r)[3]) : "r"(addr))

#define MMA_F16(d, a, b0, b1)                                                   \
    asm volatile("mma.sync.aligned.m16n8k16.row.col.f32.f16.f16.f32 "           \
        "{%0,%1,%2,%3}, {%4,%5,%6,%7}, {%8,%9}, {%0,%1,%2,%3};"                 \
        : "+f"((d)[0]), "+f"((d)[1]), "+f"((d)[2]), "+f"((d)[3])                \
        : "r"((a)[0]), "r"((a)[1]), "r"((a)[2]), "r"((a)[3]), "r"(b0), "r"(b1))

// ---------------------------------------------------------------------------
// Kernel 1 (fused): blocks [0,2304): gather -> g_A2 (k-major swizzled)
//                   blocks [2304,2592): proj_w -> g_B2 (k-major swizzled)
// ---------------------------------------------------------------------------
template <int S>
__device__ __forceinline__ void convert_pairs(const float (&e)[20], unsigned (&uh)[8]) {
#pragma unroll
    for (int k = 0; k < 8; k++) {
        __half2 hp = __halves2half2(__float2half_rn(e[S + 2 * k]),
                                    __float2half_rn(e[S + 2 * k + 1]));
        uh[k] = *reinterpret_cast<unsigned*>(&hp);
    }
}

__global__ __launch_bounds__(256) void prep_kernel(const float* __restrict__ x,
                                                   const int* __restrict__ h_idx,
                                                   const int* __restrict__ w_idx,
                                                   const float* __restrict__ pw) {
    if (blockIdx.x >= 2304) {
        // ---- B prep: one thread per 16B quad (8 floats -> 8 fp16) ----
        int i = (blockIdx.x - 2304) * 256 + threadIdx.x;   // [0, 73728)
        int e  = i / 96;            // output row 0..767
        int g  = i - e * 96;        // quad-in-row 0..95
        int kt2 = g >> 3, q = g & 7;
        const float4* s = reinterpret_cast<const float4*>(pw + (size_t)e * KDIM + kt2 * 64 + q * 8);
        float4 v0 = s[0], v1 = s[1];
        __half2 h0 = __halves2half2(__float2half_rn(v0.x), __float2half_rn(v0.y));
        __half2 h1 = __halves2half2(__float2half_rn(v0.z), __float2half_rn(v0.w));
        __half2 h2 = __halves2half2(__float2half_rn(v1.x), __float2half_rn(v1.y));
        __half2 h3 = __halves2half2(__float2half_rn(v1.z), __float2half_rn(v1.w));
        __half* dst = g_B2 + ((size_t)kt2 * EMBED + e) * 64 + ((q ^ (e & 7)) << 3);
        *reinterpret_cast<uint4*>(dst) = make_uint4(
            *reinterpret_cast<unsigned*>(&h0), *reinterpret_cast<unsigned*>(&h1),
            *reinterpret_cast<unsigned*>(&h2), *reinterpret_cast<unsigned*>(&h3));
        return;
    }
    // ---- gather: one warp per patch ----
    int warp = (blockIdx.x << 3) + (threadIdx.x >> 5);   // 0..18431
    int lane = threadIdx.x & 31;
    int b = warp / NPATCH;
    int h = h_idx[warp];
    int w = w_idx[warp];
    int s  = w & 3;
    int a0 = w & ~3;
    int p7 = warp & 7;
    const float* xb = x + (size_t)b * (3 * 384 * 384);

#pragma unroll
    for (int pass = 0; pass < 2; ++pass) {
        int rr = (pass << 5) + lane;          // row task 0..47  (c*16 + ph)
        if (rr < 48) {
            int c = rr >> 4, ph = rr & 15;
            const float4* src = reinterpret_cast<const float4*>(
                xb + (size_t)(c * 384 + h + ph) * 384 + a0);
            float4 f0 = src[0], f1 = src[1], f2 = src[2], f3 = src[3];
            float4 f4 = make_float4(0.f, 0.f, 0.f, 0.f);
            if (s != 0) f4 = src[4];
            float e[20] = {f0.x, f0.y, f0.z, f0.w, f1.x, f1.y, f1.z, f1.w,
                           f2.x, f2.y, f2.z, f2.w, f3.x, f3.y, f3.z, f3.w,
                           f4.x, f4.y, f4.z, f4.w};
            unsigned uh[8];
            switch (s) {
                case 0:  convert_pairs<0>(e, uh); break;
                case 1:  convert_pairs<1>(e, uh); break;
                case 2:  convert_pairs<2>(e, uh); break;
                default: convert_pairs<3>(e, uh); break;
            }
            int kt2 = rr >> 2, q0 = (rr & 3) * 2;
            __half* dst = g_A2 + ((size_t)kt2 * MTOT + warp) * 64;
            *reinterpret_cast<uint4*>(dst + ((q0 ^ p7) << 3)) =
                make_uint4(uh[0], uh[1], uh[2], uh[3]);
            *reinterpret_cast<uint4*>(dst + (((q0 + 1) ^ p7) << 3)) =
                make_uint4(uh[4], uh[5], uh[6], uh[7]);
        }
    }
}

// ---------------------------------------------------------------------------
// Kernel 2: GEMM. BM=128, BN=128, BK=64, 8 warps (4m x 2n), 2 CTAs/SM.
// cp.async.bulk staging + FULL/EMPTY mbarrier ring (no __syncthreads in loop):
// warps drift up to one super-ktile apart, de-phasing LDSM bursts against MMA
// bursts (R9 showed crossbar and tensor each ~55% but serialized by convoys).
// ---------------------------------------------------------------------------
static constexpr int SLOT_BYTES = 32768;     // A 16KB + B 16KB
static constexpr int N_SLOT = 3;
static constexpr int GEMM_SMEM = 128 + N_SLOT * SLOT_BYTES;  // 98432 (2 CTAs/SM)

__device__ __forceinline__ void load_frags(uint32_t (&fa)[2][4], uint32_t (&fb)[4][4],
                                           uint32_t a_base, uint32_t b_base, uint32_t xq) {
    LDSM_X4(fa[0], a_base + xq);
    LDSM_X4(fa[1], a_base + 2048 + xq);
#pragma unroll
    for (int nb = 0; nb < 4; nb++) LDSM_X4(fb[nb], b_base + nb * 2048 + xq);
}

__device__ __forceinline__ void mma_all(float (&acc)[2][8][4],
                                        uint32_t (&fa)[2][4], uint32_t (&fb)[4][4]) {
#pragma unroll
    for (int mf = 0; mf < 2; mf++)
#pragma unroll
        for (int nf = 0; nf < 8; nf++) {
            int nb = nf >> 1, sel = nf & 1;
            MMA_F16(acc[mf][nf], fa[mf], fb[nb][sel], fb[nb][2 + sel]);
        }
}

__global__ __launch_bounds__(256, 2) void gemm_kernel(const float* __restrict__ proj_b,
                                                      float* __restrict__ out) {
    extern __shared__ char smem[];
    uint32_t sb = smem_u32(smem);
    int tid = threadIdx.x;
    int lane = tid & 31, wid = tid >> 5;
    int wm = wid & 3, wn = wid >> 2;
    int nbase = blockIdx.x * 128;      // x fastest: 6 CTAs share one A tile in L2
    int mbase = blockIdx.y * 128;

    // mbarriers: full[s] at sb + s*8, empty[s] at sb + 24 + s*8
    const uint32_t FULL0 = sb, EMPTY0 = sb + 24;

    float acc[2][8][4];
#pragma unroll
    for (int a = 0; a < 2; a++)
#pragma unroll
        for (int b = 0; b < 8; b++)
#pragma unroll
            for (int c = 0; c < 4; c++) acc[a][b][c] = 0.f;

    int l15 = lane & 15, kh = lane >> 4, l7 = lane & 7;
    uint32_t base = sb + 128;
    uint32_t a_off = base + (uint32_t)((wm * 32 + l15) * 128);          // A at slot+0
    uint32_t b_off = base + 16384 + (uint32_t)((wn * 64 + l15) * 128);  // B at slot+16KB
    uint32_t xq[4];
#pragma unroll
    for (int ks = 0; ks < 4; ks++) xq[ks] = (uint32_t)(((ks * 2 + kh) ^ l7) << 4);

    const char* srcA = reinterpret_cast<const char*>(g_A2) + (size_t)mbase * 128;
    const char* srcB = reinterpret_cast<const char*>(g_B2) + (size_t)nbase * 128;
    const size_t strideA = (size_t)MTOT * 128;
    const size_t strideB = (size_t)EMBED * 128;

    if (tid == 0) {
#pragma unroll
        for (int s = 0; s < N_SLOT; s++) {
            MBAR_INIT(FULL0 + s * 8, 1u);   // tx-based completion
            MBAR_INIT(EMPTY0 + s * 8, 8u);  // one arrive per warp
        }
    }
    __syncthreads();   // only CTA-wide barrier: after init
    if (tid == 0) {
#pragma unroll
        for (int s = 0; s < 2; s++) {       // prefetch tiles 0,1
            MBAR_EXPECT_TX(FULL0 + s * 8, (uint32_t)SLOT_BYTES);
            BULK_G2S(base + s * SLOT_BYTES,         srcA + s * strideA, 16384u, FULL0 + s * 8);
            BULK_G2S(base + s * SLOT_BYTES + 16384, srcB + s * strideB, 16384u, FULL0 + s * 8);
        }
    }

    uint32_t xa[2][4], xb[4][4];   // fragment buffer X
    uint32_t ya[2][4], yb[4][4];   // fragment buffer Y

    MBAR_WAIT_PARITY(FULL0, 0);
    load_frags(xa, xb, a_off, b_off, xq[0]);

#pragma unroll
    for (int kt = 0; kt < NKT2; kt++) {
        const int s = kt % N_SLOT;
        const uint32_t slot = (uint32_t)(s * SLOT_BYTES);
        // Producer: refill slot (kt+2)%3 for tile kt+2 once all warps released it
        // (its previous readers were tile kt-1; they arrive at EMPTY after xq3).
        if (kt + 2 < NKT2 && tid == 0) {
            const int t = kt + 2, ps = t % N_SLOT, u = t / N_SLOT;
            if (u >= 1) MBAR_WAIT_PARITY(EMPTY0 + ps * 8, (u - 1) & 1);
            FENCE_ASYNC();
            MBAR_EXPECT_TX(FULL0 + ps * 8, (uint32_t)SLOT_BYTES);
            BULK_G2S(base + ps * SLOT_BYTES,         srcA + (size_t)t * strideA, 16384u, FULL0 + ps * 8);
            BULK_G2S(base + ps * SLOT_BYTES + 16384, srcB + (size_t)t * strideB, 16384u, FULL0 + ps * 8);
        }
        // 4 k16-steps, X/Y alternating; LDSM hidden under 16-MMA bursts.
        load_frags(ya, yb, a_off + slot, b_off + slot, xq[1]);
        mma_all(acc, xa, xb);
        load_frags(xa, xb, a_off + slot, b_off + slot, xq[2]);
        mma_all(acc, ya, yb);
        load_frags(ya, yb, a_off + slot, b_off + slot, xq[3]);   // last read of slot s
        if (lane == 0) MBAR_ARRIVE(EMPTY0 + s * 8);              // release slot s
        mma_all(acc, xa, xb);
        if (kt < NKT2 - 1) {
            const int nt = kt + 1, nsl = nt % N_SLOT;
            MBAR_WAIT_PARITY(FULL0 + nsl * 8, (nt / N_SLOT) & 1);
            load_frags(xa, xb, a_off + (uint32_t)(nsl * SLOT_BYTES),
                       b_off + (uint32_t)(nsl * SLOT_BYTES), xq[0]);
        }
        mma_all(acc, ya, yb);
    }

    // Epilogue: acc + bias -> out
#pragma unroll
    for (int mf = 0; mf < 2; mf++) {
#pragma unroll
        for (int nf = 0; nf < 8; nf++) {
            int row = mbase + wm * 32 + mf * 16 + (lane >> 2);
            int col = nbase + wn * 64 + nf * 8 + (lane & 3) * 2;
            float2 bv = *reinterpret_cast<const float2*>(proj_b + col);
            float2 o0 = make_float2(acc[mf][nf][0] + bv.x, acc[mf][nf][1] + bv.y);
            float2 o1 = make_float2(acc[mf][nf][2] + bv.x, acc[mf][nf][3] + bv.y);
            *reinterpret_cast<float2*>(out + (size_t)row * EMBED + col) = o0;
            *reinterpret_cast<float2*>(out + (size_t)(row + 8) * EMBED + col) = o1;
        }
    }
}

// ---------------------------------------------------------------------------
// kernel_launch
// ---------------------------------------------------------------------------
extern "C" void kernel_launch(void* const* d_in, const int* in_sizes, int n_in,
                              void* d_out, int out_size) {
    const float* x      = (const float*)d_in[0];
    const int*   h_idx  = (const int*)d_in[1];
    const int*   w_idx  = (const int*)d_in[2];
    const float* proj_w = (const float*)d_in[3];
    const float* proj_b = (const float*)d_in[4];
    float* out = (float*)d_out;

    prep_kernel<<<2592, 256>>>(x, h_idx, w_idx, proj_w);  // gather + B prep fused

    cudaFuncSetAttribute(gemm_kernel, cudaFuncAttributeMaxDynamicSharedMemorySize, GEMM_SMEM);
    gemm_kernel<<<dim3(6, 144), 256, GEMM_SMEM>>>(proj_b, out);
}